// round 1
// baseline (speedup 1.0000x reference)
#include <cuda_runtime.h>

// Problem dims
#define NB 8
#define DD 32   // d1=d2=d3
#define NC 32   // in_features
#define NO 32   // out_features
// positions = NB*DD*DD*DD = 262144

typedef unsigned long long ull;

// ---------------- scratch (device globals; no allocation allowed) ----------------
__device__ float g_m1[NB*DD*DD*NC];   // [b][j][k][c]  sum over i
__device__ float g_m2[NB*DD*DD*NC];   // [b][i][k][c]  sum over j
__device__ float g_m3[NB*DD*DD*NC];   // [b][i][j][c]  sum over k
__device__ float g_mij[NB*DD*NC];     // [b][k][c]  sum over i,j
__device__ float g_mik[NB*DD*NC];     // [b][j][c]  sum over i,k
__device__ float g_mjk[NB*DD*NC];     // [b][i][c]  sum over j,k
__device__ float g_mall[NB*NC];       // [b][c]     sum over i,j,k
__device__ float g_pij[NB*DD*NO];     // [b][k][o]
__device__ float g_pik[NB*DD*NO];     // [b][j][o]
__device__ float g_pjk[NB*DD*NO];     // [b][i][o]
__device__ float g_pall[NB*NO];       // [b][o]  (includes bias)
__device__ float g_PA[NB*DD*DD*NO];   // [b][j][k][o]
__device__ float g_PB[NB*DD*DD*NO];   // [b][i][k][o]
__device__ float g_PC[NB*DD*DD*NO];   // [b][i][j][o]

// ---------------- packed f32x2 helpers ----------------
__device__ __forceinline__ ull pack_dup(float v) {
    ull r;
    asm("mov.b64 %0, {%1, %1};" : "=l"(r) : "r"(__float_as_uint(v)));
    return r;
}
__device__ __forceinline__ float2 unpack2(ull v) {
    float2 r;
    asm("mov.b64 {%0, %1}, %2;" : "=f"(r.x), "=f"(r.y) : "l"(v));
    return r;
}
#define FMA2(acc, a, b) asm("fma.rn.f32x2 %0, %1, %2, %0;" : "+l"(acc) : "l"(a), "l"(b))

// Two-row GEMV vs Ws[c][o] (shared, uniform across block -> broadcast LDS)
__device__ __forceinline__ void gemv2(const float* __restrict__ xa,
                                      const float* __restrict__ xb,
                                      const float* Ws, ull* accA, ull* accB) {
    #pragma unroll
    for (int c4 = 0; c4 < 8; c4++) {
        float4 a4 = *(const float4*)(xa + c4 * 4);
        float4 b4 = *(const float4*)(xb + c4 * 4);
        #pragma unroll
        for (int cc = 0; cc < 4; cc++) {
            float av = ((const float*)&a4)[cc];
            float bv = ((const float*)&b4)[cc];
            ull av2 = pack_dup(av);
            ull bv2 = pack_dup(bv);
            const ull* wrow = (const ull*)(Ws + (c4 * 4 + cc) * NO);
            #pragma unroll
            for (int o2 = 0; o2 < 16; o2++) {
                ull w2 = wrow[o2];
                FMA2(accA[o2], av2, w2);
                FMA2(accB[o2], bv2, w2);
            }
        }
    }
}

// ---------------- K1: axis sums m1,m2,m3 (grid 768) ----------------
__global__ __launch_bounds__(256) void k_means(const float* __restrict__ x) {
    int sel = blockIdx.x >> 8;        // 0:m1, 1:m2, 2:m3
    int blk = blockIdx.x & 255;
    int b = blk >> 5, d = blk & 31;
    int t = threadIdx.x;
    const float4* x4 = (const float4*)x;

    if (sel == 0) {
        // m1[b][j=d][k][c] = sum_i x[b][i][d][k][c]; 256 float4 per (b,j)
        float4 acc = make_float4(0.f, 0.f, 0.f, 0.f);
        #pragma unroll 8
        for (int i = 0; i < DD; i++) {
            float4 v = x4[((b * DD + i) * DD + d) * 256 + t];
            acc.x += v.x; acc.y += v.y; acc.z += v.z; acc.w += v.w;
        }
        ((float4*)g_m1)[(b * DD + d) * 256 + t] = acc;
    } else if (sel == 1) {
        // m2[b][i=d][k][c] = sum_j x[b][d][j][k][c]
        float4 acc = make_float4(0.f, 0.f, 0.f, 0.f);
        #pragma unroll 8
        for (int j = 0; j < DD; j++) {
            float4 v = x4[((b * DD + d) * DD + j) * 256 + t];
            acc.x += v.x; acc.y += v.y; acc.z += v.z; acc.w += v.w;
        }
        ((float4*)g_m2)[(b * DD + d) * 256 + t] = acc;
    } else {
        // m3[b][i=d][j][c] = sum_k x[b][d][j][k][c]; thread: (j, c4)
        int j = t >> 3, c4 = t & 7;
        float4 acc = make_float4(0.f, 0.f, 0.f, 0.f);
        #pragma unroll 8
        for (int k = 0; k < DD; k++) {
            float4 v = x4[((b * DD + d) * DD + j) * 256 + k * 8 + c4];
            acc.x += v.x; acc.y += v.y; acc.z += v.z; acc.w += v.w;
        }
        ((float4*)g_m3)[(b * DD + d) * 256 + j * 8 + c4] = acc;
    }
}

// ---------------- K2: 2-axis & 3-axis sums (grid 96 + 256 = 352) ----------------
__global__ __launch_bounds__(256) void k_pool2(void) {
    int gid = blockIdx.x;
    if (gid < 96) {
        int id = gid * 256 + threadIdx.x;   // 0..24575
        if (id < 8192) {                     // mij[b][k][c] = sum_j m1[b][j][k][c]
            int b = id >> 10, kc = id & 1023;
            float s = 0.f;
            #pragma unroll 8
            for (int j = 0; j < DD; j++) s += g_m1[b * 32768 + j * 1024 + kc];
            g_mij[id] = s;
        } else if (id < 16384) {             // mik[b][j][c] = sum_k m1[b][j][k][c]
            int id2 = id - 8192;
            int b = id2 >> 10, j = (id2 >> 5) & 31, c = id2 & 31;
            float s = 0.f;
            #pragma unroll 8
            for (int k = 0; k < DD; k++) s += g_m1[b * 32768 + j * 1024 + k * 32 + c];
            g_mik[id2] = s;
        } else {                             // mjk[b][i][c] = sum_k m2[b][i][k][c]
            int id2 = id - 16384;
            int b = id2 >> 10, i = (id2 >> 5) & 31, c = id2 & 31;
            float s = 0.f;
            #pragma unroll 8
            for (int k = 0; k < DD; k++) s += g_m2[b * 32768 + i * 1024 + k * 32 + c];
            g_mjk[id2] = s;
        }
    } else {
        // mall[b][c] = sum_{j,k} m1[b][j][k][c]; block per (b,c)
        __shared__ float red[256];
        int bb = gid - 96;
        int b = bb >> 5, c = bb & 31;
        int t = threadIdx.x;
        float s = 0.f;
        #pragma unroll
        for (int q = 0; q < 4; q++) {
            int jk = t * 4 + q;
            s += g_m1[b * 32768 + jk * 32 + c];
        }
        red[t] = s;
        __syncthreads();
        for (int step = 128; step > 0; step >>= 1) {
            if (t < step) red[t] += red[t + step];
            __syncthreads();
        }
        if (t == 0) g_mall[b * 32 + c] = red[0];
    }
}

// ---------------- K3: small projections pij/pik/pjk/pall (grid 97) ----------------
__global__ __launch_bounds__(256) void k_smallproj(const float* __restrict__ W,
                                                   const float* __restrict__ bias) {
    int id = blockIdx.x * 256 + threadIdx.x;
    if (id < 8192) {                 // pij: group (1,2) -> W cols [128,160)
        int b = id >> 10, k = (id >> 5) & 31, o = id & 31;
        const float* m = g_mij + b * 1024 + k * 32;
        const float* w = W + o * 256 + 128;
        float s = 0.f;
        #pragma unroll
        for (int c = 0; c < NC; c++) s += m[c] * w[c];
        g_pij[id] = s * (1.0f / 1024.0f);
    } else if (id < 16384) {         // pik: group (1,3) -> [160,192)
        int id2 = id - 8192;
        int b = id2 >> 10, j = (id2 >> 5) & 31, o = id2 & 31;
        const float* m = g_mik + b * 1024 + j * 32;
        const float* w = W + o * 256 + 160;
        float s = 0.f;
        #pragma unroll
        for (int c = 0; c < NC; c++) s += m[c] * w[c];
        g_pik[id2] = s * (1.0f / 1024.0f);
    } else if (id < 24576) {         // pjk: group (2,3) -> [192,224)
        int id2 = id - 16384;
        int b = id2 >> 10, i = (id2 >> 5) & 31, o = id2 & 31;
        const float* m = g_mjk + b * 1024 + i * 32;
        const float* w = W + o * 256 + 192;
        float s = 0.f;
        #pragma unroll
        for (int c = 0; c < NC; c++) s += m[c] * w[c];
        g_pjk[id2] = s * (1.0f / 1024.0f);
    } else {                         // pall: group (1,2,3) -> [224,256), + bias
        int id2 = id - 24576;        // 0..255
        int b = id2 >> 5, o = id2 & 31;
        const float* m = g_mall + b * 32;
        const float* w = W + o * 256 + 224;
        float s = 0.f;
        #pragma unroll
        for (int c = 0; c < NC; c++) s += m[c] * w[c];
        g_pall[id2] = s * (1.0f / 32768.0f) + bias[o];
    }
}

// ---------------- K4: PA/PB/PC projections of m1/m2/m3 (grid 48) ----------------
__device__ __forceinline__ void store_P(int sel, int p, ull* acc) {
    int b = p >> 10, d1 = (p >> 5) & 31, d2 = p & 31;
    float addv[NO];
    #pragma unroll
    for (int o = 0; o < NO; o++) addv[o] = 0.f;
    float* dst;
    if (sel == 0) {
        dst = g_PA + p * 32;
        const float* px = g_pij + (b * 32 + d2) * 32;  // [b][k]
        const float* py = g_pik + (b * 32 + d1) * 32;  // [b][j]
        const float* pz = g_pall + b * 32;
        #pragma unroll
        for (int o = 0; o < NO; o++) addv[o] = px[o] + py[o] + pz[o];
    } else if (sel == 1) {
        dst = g_PB + p * 32;
        const float* px = g_pjk + (b * 32 + d1) * 32;  // [b][i]
        #pragma unroll
        for (int o = 0; o < NO; o++) addv[o] = px[o];
    } else {
        dst = g_PC + p * 32;
    }
    #pragma unroll
    for (int o2 = 0; o2 < 16; o2++) {
        float2 v = unpack2(acc[o2]);
        dst[o2 * 2]     = v.x + addv[o2 * 2];
        dst[o2 * 2 + 1] = v.y + addv[o2 * 2 + 1];
    }
}

__global__ __launch_bounds__(256) void k_bigproj(const float* __restrict__ W) {
    int sel = blockIdx.x >> 4;       // 0: PA(m1,g1)  1: PB(m2,g2)  2: PC(m3,g3)
    int blk = blockIdx.x & 15;
    __shared__ float Ws[NC * NO];    // [c][o], pre-scaled by 1/32 (mean over one axis triple-counted handled upstream)
    {
        int idx = threadIdx.x;
        #pragma unroll
        for (int q = 0; q < 4; q++, idx += 256) {
            int c = idx >> 5, o = idx & 31;
            Ws[idx] = W[o * 256 + (1 + sel) * 32 + c] * (1.0f / 32.0f);
        }
    }
    __syncthreads();
    const float* src = (sel == 0) ? g_m1 : (sel == 1) ? g_m2 : g_m3;
    int p0 = blk * 512 + threadIdx.x;
    int p1 = p0 + 256;
    ull accA[16], accB[16];
    #pragma unroll
    for (int o2 = 0; o2 < 16; o2++) { accA[o2] = 0ull; accB[o2] = 0ull; }
    gemv2(src + p0 * 32, src + p1 * 32, Ws, accA, accB);
    store_P(sel, p0, accA);
    store_P(sel, p1, accB);
}

// ---------------- K5: main projection + broadcast adds (grid 512) ----------------
__device__ __forceinline__ void epilogue_main(int p, ull* acc, float* __restrict__ out) {
    int b = p >> 15, i = (p >> 10) & 31, j = (p >> 5) & 31, k = p & 31;
    const float4* pa = (const float4*)(g_PA + (((b * 32 + j) * 32 + k) * 32));
    const float4* pb = (const float4*)(g_PB + (((b * 32 + i) * 32 + k) * 32));
    const float4* pc = (const float4*)(g_PC + (((b * 32 + i) * 32 + j) * 32));
    float4* dst = (float4*)(out + p * 32);
    #pragma unroll
    for (int o4 = 0; o4 < 8; o4++) {
        float2 v0 = unpack2(acc[o4 * 2]);
        float2 v1 = unpack2(acc[o4 * 2 + 1]);
        float4 a = pa[o4], bq = pb[o4], c = pc[o4];
        float4 r;
        r.x = v0.x + a.x + bq.x + c.x;
        r.y = v0.y + a.y + bq.y + c.y;
        r.z = v1.x + a.z + bq.z + c.z;
        r.w = v1.y + a.w + bq.w + c.w;
        dst[o4] = r;
    }
}

__global__ __launch_bounds__(256) void k_main(const float* __restrict__ x,
                                              const float* __restrict__ W,
                                              float* __restrict__ out) {
    __shared__ float Ws[NC * NO];    // [c][o] for group 0
    {
        int idx = threadIdx.x;
        #pragma unroll
        for (int q = 0; q < 4; q++, idx += 256) {
            int c = idx >> 5, o = idx & 31;
            Ws[idx] = W[o * 256 + c];
        }
    }
    __syncthreads();
    int p0 = blockIdx.x * 512 + threadIdx.x;
    int p1 = p0 + 256;
    ull accA[16], accB[16];
    #pragma unroll
    for (int o2 = 0; o2 < 16; o2++) { accA[o2] = 0ull; accB[o2] = 0ull; }
    gemv2(x + p0 * 32, x + p1 * 32, Ws, accA, accB);
    epilogue_main(p0, accA, out);
    epilogue_main(p1, accB, out);
}

// ---------------- launch ----------------
extern "C" void kernel_launch(void* const* d_in, const int* in_sizes, int n_in,
                              void* d_out, int out_size) {
    const float* x    = (const float*)d_in[0];
    const float* W    = (const float*)d_in[1];
    const float* bias = (const float*)d_in[2];
    float* out = (float*)d_out;

    k_means<<<768, 256>>>(x);
    k_pool2<<<352, 256>>>();
    k_smallproj<<<97, 256>>>(W, bias);
    k_bigproj<<<48, 256>>>(W);
    k_main<<<512, 256>>>(x, W, out);
}

// round 2
// speedup vs baseline: 1.2997x; 1.2997x over previous
#include <cuda_runtime.h>

// Problem dims
#define NB 8
#define DD 32   // d1=d2=d3
#define NC 32   // in_features
#define NO 32   // out_features
// positions = NB*DD*DD*DD = 262144

typedef unsigned long long ull;

// ---------------- scratch (device globals; no allocation allowed) ----------------
__device__ float g_m1[NB*DD*DD*NC];   // [b][j][k][c]  sum over i
__device__ float g_m2[NB*DD*DD*NC];   // [b][i][k][c]  sum over j
__device__ float g_m3[NB*DD*DD*NC];   // [b][i][j][c]  sum over k
__device__ float g_pij[NB*DD*NO];     // [b][k][o]
__device__ float g_pik[NB*DD*NO];     // [b][j][o]
__device__ float g_pjk[NB*DD*NO];     // [b][i][o]
__device__ float g_pall[NB*NO];       // [b][o]  (includes bias)
__device__ float g_PA[NB*DD*DD*NO];   // [b][j][k][o]
__device__ float g_PB[NB*DD*DD*NO];   // [b][i][k][o]
__device__ float g_PC[NB*DD*DD*NO];   // [b][i][j][o]

// ---------------- packed f32x2 helpers ----------------
__device__ __forceinline__ ull pack_dup(float v) {
    ull r;
    asm("mov.b64 %0, {%1, %1};" : "=l"(r) : "r"(__float_as_uint(v)));
    return r;
}
__device__ __forceinline__ float2 unpack2(ull v) {
    float2 r;
    asm("mov.b64 {%0, %1}, %2;" : "=f"(r.x), "=f"(r.y) : "l"(v));
    return r;
}
#define FMA2(acc, a, b) asm("fma.rn.f32x2 %0, %1, %2, %0;" : "+l"(acc) : "l"(a), "l"(b))

// Two-row GEMV vs Ws[c][o] (shared, uniform across block -> broadcast LDS)
__device__ __forceinline__ void gemv2(const float* __restrict__ xa,
                                      const float* __restrict__ xb,
                                      const float* Ws, ull* accA, ull* accB) {
    #pragma unroll
    for (int c4 = 0; c4 < 8; c4++) {
        float4 a4 = *(const float4*)(xa + c4 * 4);
        float4 b4 = *(const float4*)(xb + c4 * 4);
        #pragma unroll
        for (int cc = 0; cc < 4; cc++) {
            float av = ((const float*)&a4)[cc];
            float bv = ((const float*)&b4)[cc];
            ull av2 = pack_dup(av);
            ull bv2 = pack_dup(bv);
            const ull* wrow = (const ull*)(Ws + (c4 * 4 + cc) * NO);
            #pragma unroll
            for (int o2 = 0; o2 < 16; o2++) {
                ull w2 = wrow[o2];
                FMA2(accA[o2], av2, w2);
                FMA2(accB[o2], bv2, w2);
            }
        }
    }
}

// ---------------- K1: axis sums m1,m2,m3 (grid 768) ----------------
__global__ __launch_bounds__(256) void k_means(const float* __restrict__ x) {
    int sel = blockIdx.x >> 8;        // 0:m1, 1:m2, 2:m3
    int blk = blockIdx.x & 255;
    int b = blk >> 5, d = blk & 31;
    int t = threadIdx.x;
    const float4* x4 = (const float4*)x;

    if (sel == 0) {
        // m1[b][j=d][k][c] = sum_i x[b][i][d][k][c]; 256 float4 per (b,j)
        float4 acc = make_float4(0.f, 0.f, 0.f, 0.f);
        #pragma unroll 8
        for (int i = 0; i < DD; i++) {
            float4 v = x4[((b * DD + i) * DD + d) * 256 + t];
            acc.x += v.x; acc.y += v.y; acc.z += v.z; acc.w += v.w;
        }
        ((float4*)g_m1)[(b * DD + d) * 256 + t] = acc;
    } else if (sel == 1) {
        // m2[b][i=d][k][c] = sum_j x[b][d][j][k][c]
        float4 acc = make_float4(0.f, 0.f, 0.f, 0.f);
        #pragma unroll 8
        for (int j = 0; j < DD; j++) {
            float4 v = x4[((b * DD + d) * DD + j) * 256 + t];
            acc.x += v.x; acc.y += v.y; acc.z += v.z; acc.w += v.w;
        }
        ((float4*)g_m2)[(b * DD + d) * 256 + t] = acc;
    } else {
        // m3[b][i=d][j][c] = sum_k x[b][d][j][k][c]; thread: (j, c4)
        int j = t >> 3, c4 = t & 7;
        float4 acc = make_float4(0.f, 0.f, 0.f, 0.f);
        #pragma unroll 8
        for (int k = 0; k < DD; k++) {
            float4 v = x4[((b * DD + d) * DD + j) * 256 + k * 8 + c4];
            acc.x += v.x; acc.y += v.y; acc.z += v.z; acc.w += v.w;
        }
        ((float4*)g_m3)[(b * DD + d) * 256 + j * 8 + c4] = acc;
    }
}

// ---------------- K2: fused 2/3-axis pools + small projections (grid 776) ----------------
// blocks [0,256):   pij[b][k][o]  from sum_j m1[b][j][k][:]
// blocks [256,512): pik[b][j][o]  from sum_k m1[b][j][k][:]
// blocks [512,768): pjk[b][i][o]  from sum_k m2[b][i][k][:]
// blocks [768,776): pall[b][o]    from sum_jk m1[b][jk][:] (+bias)
__global__ __launch_bounds__(128) void k_small(const float* __restrict__ W,
                                               const float* __restrict__ bias) {
    __shared__ float part[128];
    __shared__ float mrow[NC];
    int gid = blockIdx.x;
    int t = threadIdx.x;
    int c = t & 31, q = t >> 5;     // q in 0..3

    float s = 0.f;
    const float* w;
    float scale;
    float* dst;
    bool addb = false;

    if (gid < 256) {
        int b = gid >> 5, k = gid & 31;
        #pragma unroll
        for (int j = q; j < DD; j += 4) s += g_m1[((b * DD + j) * DD + k) * NC + c];
        w = W + 128; scale = 1.0f / 1024.0f; dst = g_pij + gid * NO;
    } else if (gid < 512) {
        int g = gid - 256;
        int b = g >> 5, j = g & 31;
        #pragma unroll
        for (int k = q; k < DD; k += 4) s += g_m1[((b * DD + j) * DD + k) * NC + c];
        w = W + 160; scale = 1.0f / 1024.0f; dst = g_pik + g * NO;
    } else if (gid < 768) {
        int g = gid - 512;
        int b = g >> 5, i = g & 31;
        #pragma unroll
        for (int k = q; k < DD; k += 4) s += g_m2[((b * DD + i) * DD + k) * NC + c];
        w = W + 192; scale = 1.0f / 1024.0f; dst = g_pjk + g * NO;
    } else {
        int b = gid - 768;
        for (int jk = q; jk < DD * DD; jk += 4) s += g_m1[(b * DD * DD + jk) * NC + c];
        w = W + 224; scale = 1.0f / 32768.0f; dst = g_pall + b * NO; addb = true;
    }
    part[t] = s;
    __syncthreads();
    if (t < 32) {
        mrow[t] = part[t] + part[t + 32] + part[t + 64] + part[t + 96];
    }
    __syncthreads();
    if (t < 32) {
        float acc = 0.f;
        #pragma unroll
        for (int cc = 0; cc < NC; cc++) acc += mrow[cc] * w[t * 256 + cc];
        acc *= scale;
        if (addb) acc += bias[t];
        dst[t] = acc;
    }
}

// ---------------- K3: PA/PB/PC projections of m1/m2/m3 (grid 192) ----------------
// thread = (row, output-half): 128 rows x 2 halves per 256-thread block
__global__ __launch_bounds__(256) void k_bigproj(const float* __restrict__ W) {
    int sel = blockIdx.x >> 6;       // 64 blocks per source (8192 rows each)
    __shared__ float Ws[NC * NO];    // [c][o], pre-scaled by 1/32
    {
        int idx = threadIdx.x;
        #pragma unroll
        for (int qq = 0; qq < 4; qq++, idx += 256) {
            int c = idx >> 5, o = idx & 31;
            Ws[idx] = W[o * 256 + (1 + sel) * 32 + c] * (1.0f / 32.0f);
        }
    }
    __syncthreads();

    int p = (blockIdx.x & 63) * 128 + (threadIdx.x >> 1);   // row within source
    int half = threadIdx.x & 1;                              // outputs [half*16, half*16+16)
    const float* src = (sel == 0) ? g_m1 : (sel == 1) ? g_m2 : g_m3;
    const float4* xr = (const float4*)(src + p * NC);

    ull acc[8];
    #pragma unroll
    for (int o2 = 0; o2 < 8; o2++) acc[o2] = 0ull;

    #pragma unroll
    for (int c4 = 0; c4 < 8; c4++) {
        float4 a4 = xr[c4];
        #pragma unroll
        for (int cc = 0; cc < 4; cc++) {
            ull av2 = pack_dup(((const float*)&a4)[cc]);
            const ull* wrow = (const ull*)(Ws + (c4 * 4 + cc) * NO + half * 16);
            #pragma unroll
            for (int o2 = 0; o2 < 8; o2++) FMA2(acc[o2], av2, wrow[o2]);
        }
    }

    int b = p >> 10, d1 = (p >> 5) & 31, d2 = p & 31;
    float add[16];
    #pragma unroll
    for (int o = 0; o < 16; o++) add[o] = 0.f;
    float* dst;
    if (sel == 0) {
        dst = g_PA;
        const float* px = g_pij + (b * 32 + d2) * NO + half * 16;  // [b][k]
        const float* py = g_pik + (b * 32 + d1) * NO + half * 16;  // [b][j]
        const float* pz = g_pall + b * NO + half * 16;
        #pragma unroll
        for (int o = 0; o < 16; o++) add[o] = px[o] + py[o] + pz[o];
    } else if (sel == 1) {
        dst = g_PB;
        const float* px = g_pjk + (b * 32 + d1) * NO + half * 16;  // [b][i]
        #pragma unroll
        for (int o = 0; o < 16; o++) add[o] = px[o];
    } else {
        dst = g_PC;
    }

    float4* dv = (float4*)(dst + p * NO + half * 16);
    #pragma unroll
    for (int o4 = 0; o4 < 4; o4++) {
        float2 v0 = unpack2(acc[o4 * 2]);
        float2 v1 = unpack2(acc[o4 * 2 + 1]);
        float4 r;
        r.x = v0.x + add[o4 * 4 + 0];
        r.y = v0.y + add[o4 * 4 + 1];
        r.z = v1.x + add[o4 * 4 + 2];
        r.w = v1.y + add[o4 * 4 + 3];
        dv[o4] = r;
    }
}

// ---------------- K4: main projection + broadcast adds (grid 1024 x 128) ----------------
__device__ __forceinline__ void epilogue_main(int p, ull* acc, float* __restrict__ out) {
    int b = p >> 15, i = (p >> 10) & 31, j = (p >> 5) & 31, k = p & 31;
    const float4* pa = (const float4*)(g_PA + (((b * 32 + j) * 32 + k) * 32));
    const float4* pb = (const float4*)(g_PB + (((b * 32 + i) * 32 + k) * 32));
    const float4* pc = (const float4*)(g_PC + (((b * 32 + i) * 32 + j) * 32));
    float4* dst = (float4*)(out + p * 32);
    #pragma unroll
    for (int o4 = 0; o4 < 8; o4++) {
        float2 v0 = unpack2(acc[o4 * 2]);
        float2 v1 = unpack2(acc[o4 * 2 + 1]);
        float4 a = pa[o4], bq = pb[o4], c = pc[o4];
        float4 r;
        r.x = v0.x + a.x + bq.x + c.x;
        r.y = v0.y + a.y + bq.y + c.y;
        r.z = v1.x + a.z + bq.z + c.z;
        r.w = v1.y + a.w + bq.w + c.w;
        dst[o4] = r;
    }
}

__global__ __launch_bounds__(128) void k_main(const float* __restrict__ x,
                                              const float* __restrict__ W,
                                              float* __restrict__ out) {
    __shared__ float Ws[NC * NO];    // [c][o] for group 0
    {
        int idx = threadIdx.x;
        #pragma unroll
        for (int qq = 0; qq < 8; qq++, idx += 128) {
            int c = idx >> 5, o = idx & 31;
            Ws[idx] = W[o * 256 + c];
        }
    }
    __syncthreads();
    int p0 = blockIdx.x * 256 + threadIdx.x;
    int p1 = p0 + 128;
    ull accA[16], accB[16];
    #pragma unroll
    for (int o2 = 0; o2 < 16; o2++) { accA[o2] = 0ull; accB[o2] = 0ull; }
    gemv2(x + p0 * 32, x + p1 * 32, Ws, accA, accB);
    epilogue_main(p0, accA, out);
    epilogue_main(p1, accB, out);
}

// ---------------- launch ----------------
extern "C" void kernel_launch(void* const* d_in, const int* in_sizes, int n_in,
                              void* d_out, int out_size) {
    const float* x    = (const float*)d_in[0];
    const float* W    = (const float*)d_in[1];
    const float* bias = (const float*)d_in[2];
    float* out = (float*)d_out;

    k_means<<<768, 256>>>(x);
    k_small<<<776, 128>>>(W, bias);
    k_bigproj<<<192, 256>>>(W);
    k_main<<<1024, 128>>>(x, W, out);
}

// round 3
// speedup vs baseline: 1.8935x; 1.4569x over previous
#include <cuda_runtime.h>

// Problem dims
#define NB 8
#define DD 32   // d1=d2=d3
#define NC 32   // in_features
#define NO 32   // out_features
// positions = NB*DD*DD*DD = 262144

typedef unsigned long long ull;

// ---------------- scratch (device globals; no allocation allowed) ----------------
__device__ float g_m1[NB*DD*DD*NC];   // [b][j][k][c]  sum over i
__device__ float g_m2[NB*DD*DD*NC];   // [b][i][k][c]  sum over j
__device__ float g_m3[NB*DD*DD*NC];   // [b][i][j][c]  sum over k
__device__ float g_pij[NB*DD*NO];     // [b][k][o]
__device__ float g_pik[NB*DD*NO];     // [b][j][o]
__device__ float g_pjk[NB*DD*NO];     // [b][i][o]
__device__ float g_pall[NB*NO];       // [b][o]  (includes bias)
__device__ float g_PA[NB*DD*DD*NO];   // [b][j][k][o]
__device__ float g_PB[NB*DD*DD*NO];   // [b][i][k][o]
__device__ float g_PC[NB*DD*DD*NO];   // [b][i][j][o]

// ---------------- packed f32x2 helpers ----------------
__device__ __forceinline__ ull pack_dup(float v) {
    ull r;
    asm("mov.b64 %0, {%1, %1};" : "=l"(r) : "r"(__float_as_uint(v)));
    return r;
}
__device__ __forceinline__ ull pack2(float a, float b) {
    ull r;
    asm("mov.b64 %0, {%1, %2};" : "=l"(r) : "r"(__float_as_uint(a)), "r"(__float_as_uint(b)));
    return r;
}
__device__ __forceinline__ float2 unpack2(ull v) {
    float2 r;
    asm("mov.b64 {%0, %1}, %2;" : "=f"(r.x), "=f"(r.y) : "l"(v));
    return r;
}
#define FMA2(acc, a, b) asm("fma.rn.f32x2 %0, %1, %2, %0;" : "+l"(acc) : "l"(a), "l"(b))

// ---------------- K1: axis sums m1,m2,m3 (grid 768) ----------------
__global__ __launch_bounds__(256) void k_means(const float* __restrict__ x) {
    int sel = blockIdx.x >> 8;        // 0:m1, 1:m2, 2:m3
    int blk = blockIdx.x & 255;
    int b = blk >> 5, d = blk & 31;
    int t = threadIdx.x;
    const float4* x4 = (const float4*)x;

    if (sel == 0) {
        float4 acc = make_float4(0.f, 0.f, 0.f, 0.f);
        #pragma unroll 8
        for (int i = 0; i < DD; i++) {
            float4 v = x4[((b * DD + i) * DD + d) * 256 + t];
            acc.x += v.x; acc.y += v.y; acc.z += v.z; acc.w += v.w;
        }
        ((float4*)g_m1)[(b * DD + d) * 256 + t] = acc;
    } else if (sel == 1) {
        float4 acc = make_float4(0.f, 0.f, 0.f, 0.f);
        #pragma unroll 8
        for (int j = 0; j < DD; j++) {
            float4 v = x4[((b * DD + d) * DD + j) * 256 + t];
            acc.x += v.x; acc.y += v.y; acc.z += v.z; acc.w += v.w;
        }
        ((float4*)g_m2)[(b * DD + d) * 256 + t] = acc;
    } else {
        int j = t >> 3, c4 = t & 7;
        float4 acc = make_float4(0.f, 0.f, 0.f, 0.f);
        #pragma unroll 8
        for (int k = 0; k < DD; k++) {
            float4 v = x4[((b * DD + d) * DD + j) * 256 + k * 8 + c4];
            acc.x += v.x; acc.y += v.y; acc.z += v.z; acc.w += v.w;
        }
        ((float4*)g_m3)[(b * DD + d) * 256 + j * 8 + c4] = acc;
    }
}

// ---------------- K2: fused 2/3-axis pools + small projections (grid 776) ----------------
__global__ __launch_bounds__(128) void k_small(const float* __restrict__ W,
                                               const float* __restrict__ bias) {
    __shared__ float part[128];
    __shared__ float mrow[NC];
    int gid = blockIdx.x;
    int t = threadIdx.x;
    int c = t & 31, q = t >> 5;     // q in 0..3

    float s = 0.f;
    const float* w;
    float scale;
    float* dst;
    bool addb = false;

    if (gid < 256) {
        int b = gid >> 5, k = gid & 31;
        #pragma unroll
        for (int j = q; j < DD; j += 4) s += g_m1[((b * DD + j) * DD + k) * NC + c];
        w = W + 128; scale = 1.0f / 1024.0f; dst = g_pij + gid * NO;
    } else if (gid < 512) {
        int g = gid - 256;
        int b = g >> 5, j = g & 31;
        #pragma unroll
        for (int k = q; k < DD; k += 4) s += g_m1[((b * DD + j) * DD + k) * NC + c];
        w = W + 160; scale = 1.0f / 1024.0f; dst = g_pik + g * NO;
    } else if (gid < 768) {
        int g = gid - 512;
        int b = g >> 5, i = g & 31;
        #pragma unroll
        for (int k = q; k < DD; k += 4) s += g_m2[((b * DD + i) * DD + k) * NC + c];
        w = W + 192; scale = 1.0f / 1024.0f; dst = g_pjk + g * NO;
    } else {
        int b = gid - 768;
        for (int jk = q; jk < DD * DD; jk += 4) s += g_m1[(b * DD * DD + jk) * NC + c];
        w = W + 224; scale = 1.0f / 32768.0f; dst = g_pall + b * NO; addb = true;
    }
    part[t] = s;
    __syncthreads();
    if (t < 32) {
        mrow[t] = part[t] + part[t + 32] + part[t + 64] + part[t + 96];
    }
    __syncthreads();
    if (t < 32) {
        float acc = 0.f;
        #pragma unroll
        for (int cc = 0; cc < NC; cc++) acc += mrow[cc] * w[t * 256 + cc];
        acc *= scale;
        if (addb) acc += bias[t];
        dst[t] = acc;
    }
}

// ---------------- K3: PA/PB/PC projections of m1/m2/m3 (grid 192) ----------------
__global__ __launch_bounds__(256) void k_bigproj(const float* __restrict__ W) {
    int sel = blockIdx.x >> 6;       // 64 blocks per source (8192 rows each)
    __shared__ float Ws[NC * NO];    // [c][o], pre-scaled by 1/32
    {
        int idx = threadIdx.x;
        #pragma unroll
        for (int qq = 0; qq < 4; qq++, idx += 256) {
            int c = idx >> 5, o = idx & 31;
            Ws[idx] = W[o * 256 + (1 + sel) * 32 + c] * (1.0f / 32.0f);
        }
    }
    __syncthreads();

    int p = (blockIdx.x & 63) * 128 + (threadIdx.x >> 1);   // row within source
    int half = threadIdx.x & 1;                              // outputs [half*16, half*16+16)
    const float* src = (sel == 0) ? g_m1 : (sel == 1) ? g_m2 : g_m3;
    const float4* xr = (const float4*)(src + p * NC);

    ull acc[8];
    #pragma unroll
    for (int o2 = 0; o2 < 8; o2++) acc[o2] = 0ull;

    #pragma unroll
    for (int c4 = 0; c4 < 8; c4++) {
        float4 a4 = xr[c4];
        #pragma unroll
        for (int cc = 0; cc < 4; cc++) {
            ull av2 = pack_dup(((const float*)&a4)[cc]);
            const ull* wrow = (const ull*)(Ws + (c4 * 4 + cc) * NO + half * 16);
            #pragma unroll
            for (int o2 = 0; o2 < 8; o2++) FMA2(acc[o2], av2, wrow[o2]);
        }
    }

    int b = p >> 10, d1 = (p >> 5) & 31, d2 = p & 31;
    float add[16];
    #pragma unroll
    for (int o = 0; o < 16; o++) add[o] = 0.f;
    float* dst;
    if (sel == 0) {
        dst = g_PA;
        const float* px = g_pij + (b * 32 + d2) * NO + half * 16;  // [b][k]
        const float* py = g_pik + (b * 32 + d1) * NO + half * 16;  // [b][j]
        const float* pz = g_pall + b * NO + half * 16;
        #pragma unroll
        for (int o = 0; o < 16; o++) add[o] = px[o] + py[o] + pz[o];
    } else if (sel == 1) {
        dst = g_PB;
        const float* px = g_pjk + (b * 32 + d1) * NO + half * 16;  // [b][i]
        #pragma unroll
        for (int o = 0; o < 16; o++) add[o] = px[o];
    } else {
        dst = g_PC;
    }

    float4* dv = (float4*)(dst + p * NO + half * 16);
    #pragma unroll
    for (int o4 = 0; o4 < 4; o4++) {
        float2 v0 = unpack2(acc[o4 * 2]);
        float2 v1 = unpack2(acc[o4 * 2 + 1]);
        float4 r;
        r.x = v0.x + add[o4 * 4 + 0];
        r.y = v0.y + add[o4 * 4 + 1];
        r.z = v1.x + add[o4 * 4 + 2];
        r.w = v1.y + add[o4 * 4 + 3];
        dv[o4] = r;
    }
}

// ---------------- K4: main projection, register-tiled (grid 1024 x 256) ----------------
// Block: 256 rows (positions) x 32 outputs. Thread (pg, og): rows pg*4..pg*4+3,
// outputs og*8..og*8+7 (4 ull accumulators per row). x staged in smem with
// stride 33 (conflict-free scalar LDS); W packed as ull pairs in smem.
#define XS 33
__global__ __launch_bounds__(256) void k_main(const float* __restrict__ x,
                                              const float* __restrict__ W,
                                              float* __restrict__ out) {
    __shared__ float x_s[256 * XS];   // [row][c], padded
    __shared__ ull   Wu[NC * 16];     // [c][o2] : (W[2*o2][c], W[2*o2+1][c])

    int tid = threadIdx.x;
    int p0 = blockIdx.x * 256;
    int b = p0 >> 15, i = (p0 >> 10) & 31, j0 = (p0 >> 5) & 31;  // block spans j0..j0+7, all k

    // ---- stage W (one-time) ----
    #pragma unroll
    for (int idx = tid; idx < 512; idx += 256) {
        int c = idx >> 4, o2 = idx & 15;
        Wu[c * 16 + o2] = pack2(W[(2 * o2) * 256 + c], W[(2 * o2 + 1) * 256 + c]);
    }
    // ---- stage x: 2048 float4, conflict-free scalar STS ----
    {
        const float4* xg = (const float4*)(x + (size_t)p0 * 32);
        #pragma unroll
        for (int pass = 0; pass < 8; pass++) {
            int idx = pass * 256 + tid;
            int row = idx >> 3, c4 = idx & 7;
            float4 v = xg[idx];
            float* d = x_s + row * XS + c4 * 4;
            d[0] = v.x; d[1] = v.y; d[2] = v.z; d[3] = v.w;
        }
    }
    __syncthreads();

    int pg = tid >> 2;          // 0..63 : row group
    int og = tid & 3;           // 0..3  : output group (8 outputs)

    const float* xr = x_s + pg * 4 * XS;
    const ull*   wp = Wu + og * 4;

    ull acc[4][4];
    #pragma unroll
    for (int r = 0; r < 4; r++)
        #pragma unroll
        for (int w = 0; w < 4; w++) acc[r][w] = 0ull;

    #pragma unroll 8
    for (int c = 0; c < NC; c++) {
        ull x0 = pack_dup(xr[c]);
        ull x1 = pack_dup(xr[XS + c]);
        ull x2 = pack_dup(xr[2 * XS + c]);
        ull x3 = pack_dup(xr[3 * XS + c]);
        ulonglong2 wa = *(const ulonglong2*)(wp + c * 16);
        ulonglong2 wb = *(const ulonglong2*)(wp + c * 16 + 2);
        FMA2(acc[0][0], x0, wa.x); FMA2(acc[0][1], x0, wa.y);
        FMA2(acc[0][2], x0, wb.x); FMA2(acc[0][3], x0, wb.y);
        FMA2(acc[1][0], x1, wa.x); FMA2(acc[1][1], x1, wa.y);
        FMA2(acc[1][2], x1, wb.x); FMA2(acc[1][3], x1, wb.y);
        FMA2(acc[2][0], x2, wa.x); FMA2(acc[2][1], x2, wa.y);
        FMA2(acc[2][2], x2, wb.x); FMA2(acc[2][3], x2, wb.y);
        FMA2(acc[3][0], x3, wa.x); FMA2(acc[3][1], x3, wa.y);
        FMA2(acc[3][2], x3, wb.x); FMA2(acc[3][3], x3, wb.y);
    }

    // ---- epilogue: + PA[b][j][k] + PB[b][i][k] + PC[b][i][j], store out ----
    #pragma unroll
    for (int r = 0; r < 4; r++) {
        int rl = pg * 4 + r;                 // 0..255
        int k = rl & 31, jj = rl >> 5;
        const float4* pa = (const float4*)(g_PA + ((((b * 32 + j0 + jj) * 32 + k) * 32) + og * 8));
        const float4* pb = (const float4*)(g_PB + ((((b * 32 + i) * 32 + k) * 32) + og * 8));
        const float4* pc = (const float4*)(g_PC + ((((b * 32 + i) * 32 + j0 + jj) * 32) + og * 8));
        float4 a0 = pa[0], a1 = pa[1];
        float4 b0 = pb[0], b1 = pb[1];
        float4 c0 = pc[0], c1 = pc[1];
        float2 v0 = unpack2(acc[r][0]);
        float2 v1 = unpack2(acc[r][1]);
        float2 v2 = unpack2(acc[r][2]);
        float2 v3 = unpack2(acc[r][3]);
        float4 r0, r1;
        r0.x = v0.x + a0.x + b0.x + c0.x;
        r0.y = v0.y + a0.y + b0.y + c0.y;
        r0.z = v1.x + a0.z + b0.z + c0.z;
        r0.w = v1.y + a0.w + b0.w + c0.w;
        r1.x = v2.x + a1.x + b1.x + c1.x;
        r1.y = v2.y + a1.y + b1.y + c1.y;
        r1.z = v3.x + a1.z + b1.z + c1.z;
        r1.w = v3.y + a1.w + b1.w + c1.w;
        float4* dst = (float4*)(out + (size_t)(p0 + rl) * 32 + og * 8);
        dst[0] = r0;
        dst[1] = r1;
    }
}

// ---------------- launch ----------------
extern "C" void kernel_launch(void* const* d_in, const int* in_sizes, int n_in,
                              void* d_out, int out_size) {
    const float* x    = (const float*)d_in[0];
    const float* W    = (const float*)d_in[1];
    const float* bias = (const float*)d_in[2];
    float* out = (float*)d_out;

    k_means<<<768, 256>>>(x);
    k_small<<<776, 128>>>(W, bias);
    k_bigproj<<<192, 256>>>(W);
    k_main<<<1024, 256>>>(x, W, out);
}